// round 16
// baseline (speedup 1.0000x reference)
#include <cuda_runtime.h>
#include <cuda_fp16.h>
#include <cstdint>
#include <math.h>

// Problem constants
#define TKN   4096
#define DDIM  1024
#define FDIM  2048
#define NEXP  8
#define NASS  (TKN * 2)

// ---------------------------------------------------------------------------
// Scratch (device globals)
// ---------------------------------------------------------------------------
__device__ int   g_counts[NEXP];
__device__ int   g_offsets[NEXP + 1];
__device__ int   g_cursor[NEXP];
__device__ int   g_rowTok[NASS];
__device__ float g_rowProb[NASS];
__device__ float g_probs[NASS];
__device__ int   g_topE[NASS];

__device__ __align__(16) __half g_xh[(size_t)TKN * DDIM];
__device__ __align__(16) __half g_W3h[(size_t)NEXP * DDIM * FDIM];
__device__ __align__(16) __half g_Hh[(size_t)NASS * FDIM];

// ---------------------------------------------------------------------------
// Helpers
// ---------------------------------------------------------------------------
__device__ __forceinline__ uint32_t smem_u32(const void* p) {
    uint32_t a;
    asm("{ .reg .u64 t; cvta.to.shared.u64 t, %1; cvt.u32.u64 %0, t; }" : "=r"(a) : "l"(p));
    return a;
}
__device__ __forceinline__ void cp16(void* dst, const void* src, int zfill) {
    uint32_t d = smem_u32(dst);
    asm volatile("cp.async.cg.shared.global [%0], [%1], 16, %2;"
                 :: "r"(d), "l"(src), "r"(zfill) : "memory");
}
#define CP_COMMIT() asm volatile("cp.async.commit_group;" ::: "memory")
#define CP_WAIT(n)  asm volatile("cp.async.wait_group %0;" :: "n"(n) : "memory")

__device__ __forceinline__ void mma_f16(float* c, const uint32_t* a,
                                        uint32_t b0, uint32_t b1) {
    asm volatile(
        "mma.sync.aligned.m16n8k16.row.col.f32.f16.f16.f32 "
        "{%0,%1,%2,%3}, {%4,%5,%6,%7}, {%8,%9}, {%0,%1,%2,%3};"
        : "+f"(c[0]), "+f"(c[1]), "+f"(c[2]), "+f"(c[3])
        : "r"(a[0]), "r"(a[1]), "r"(a[2]), "r"(a[3]), "r"(b0), "r"(b1));
}
__device__ __forceinline__ void ldsm4(uint32_t* r, uint32_t a) {
    asm volatile("ldmatrix.sync.aligned.m8n8.x4.shared.b16 {%0,%1,%2,%3}, [%4];"
                 : "=r"(r[0]), "=r"(r[1]), "=r"(r[2]), "=r"(r[3]) : "r"(a));
}

// fp32x8 -> fp16x8 packed as uint4
__device__ __forceinline__ uint4 cvt8(const float* src) {
    float4 v0 = *(const float4*)src;
    float4 v1 = *(const float4*)(src + 4);
    __half2 h0 = __floats2half2_rn(v0.x, v0.y);
    __half2 h1 = __floats2half2_rn(v0.z, v0.w);
    __half2 h2 = __floats2half2_rn(v1.x, v1.y);
    __half2 h3 = __floats2half2_rn(v1.z, v1.w);
    uint4 o;
    o.x = *reinterpret_cast<uint32_t*>(&h0);
    o.y = *reinterpret_cast<uint32_t*>(&h1);
    o.z = *reinterpret_cast<uint32_t*>(&h2);
    o.w = *reinterpret_cast<uint32_t*>(&h3);
    return o;
}

// ---------------------------------------------------------------------------
// W3 convert (pair granularity; hidden on side stream)
// ---------------------------------------------------------------------------
#define W4 (NEXP * FDIM * DDIM / 4)
#define WP ((long)W4 / 2)

__device__ __forceinline__ void cvt_pair(const float4* s, uint4* d, long j) {
    float4 a = s[2 * j], b = s[2 * j + 1];
    __half2 h0 = __floats2half2_rn(a.x, a.y);
    __half2 h1 = __floats2half2_rn(a.z, a.w);
    __half2 h2 = __floats2half2_rn(b.x, b.y);
    __half2 h3 = __floats2half2_rn(b.z, b.w);
    uint4 o;
    o.x = *reinterpret_cast<uint32_t*>(&h0);
    o.y = *reinterpret_cast<uint32_t*>(&h1);
    o.z = *reinterpret_cast<uint32_t*>(&h2);
    o.w = *reinterpret_cast<uint32_t*>(&h3);
    d[j] = o;
}

__global__ __launch_bounds__(256) void convert_w3_kernel(const float* __restrict__ W3) {
    long p0 = (long)blockIdx.x * 1024 + threadIdx.x;
    #pragma unroll
    for (int u = 0; u < 4; u++) {
        long p = p0 + u * 256;
        if (p < WP) cvt_pair((const float4*)W3, (uint4*)g_W3h, p);
    }
}

// ---------------------------------------------------------------------------
// Reset routing counters
// ---------------------------------------------------------------------------
__global__ void reset_kernel() {
    if (threadIdx.x < NEXP) {
        g_counts[threadIdx.x] = 0;
        g_cursor[threadIdx.x] = 0;
    }
}

// ---------------------------------------------------------------------------
// Gating: top-2 + softmax + counts; ALSO converts this token's x row to fp16
// ---------------------------------------------------------------------------
__global__ __launch_bounds__(256) void gating_kernel(
    const float* __restrict__ x, const float* __restrict__ Wg) {
    int t = blockIdx.x;
    __shared__ float xs[DDIM];
    __shared__ float sc[NEXP];
    for (int i = threadIdx.x; i < DDIM; i += 256)
        xs[i] = x[(size_t)t * DDIM + i];
    __syncthreads();

    {
        int i4 = threadIdx.x * 4;
        __half2 ha = __floats2half2_rn(xs[i4],     xs[i4 + 1]);
        __half2 hb = __floats2half2_rn(xs[i4 + 2], xs[i4 + 3]);
        uint2 o;
        o.x = *reinterpret_cast<uint32_t*>(&ha);
        o.y = *reinterpret_cast<uint32_t*>(&hb);
        *(uint2*)(g_xh + (size_t)t * DDIM + i4) = o;
    }

    int w = threadIdx.x >> 5, lane = threadIdx.x & 31;
    const float* wg = Wg + (size_t)w * DDIM;
    float acc = 0.f;
    #pragma unroll 8
    for (int i = lane; i < DDIM; i += 32) acc += xs[i] * wg[i];
    #pragma unroll
    for (int o = 16; o; o >>= 1) acc += __shfl_xor_sync(0xFFFFFFFFu, acc, o);
    if (lane == 0) sc[w] = acc;
    __syncthreads();
    if (threadIdx.x == 0) {
        int e0 = 0; float s0 = sc[0];
        #pragma unroll
        for (int e = 1; e < NEXP; e++)
            if (sc[e] > s0) { s0 = sc[e]; e0 = e; }
        int e1 = -1; float s1 = -1e30f;
        #pragma unroll
        for (int e = 0; e < NEXP; e++)
            if (e != e0 && sc[e] > s1) { s1 = sc[e]; e1 = e; }
        float z = expf(s1 - s0);
        float inv = 1.f / (1.f + z);
        g_topE[2 * t] = e0;  g_topE[2 * t + 1] = e1;
        g_probs[2 * t] = inv; g_probs[2 * t + 1] = z * inv;
        atomicAdd(&g_counts[e0], 1);
        atomicAdd(&g_counts[e1], 1);
    }
}

// ---------------------------------------------------------------------------
// Scatter (with local scan of the 8 expert counts); records per-row token+prob
// ---------------------------------------------------------------------------
__global__ __launch_bounds__(256) void scatter_kernel() {
    __shared__ int soff[NEXP];
    if (threadIdx.x < NEXP) {
        int o = 0;
        for (int e = 0; e < threadIdx.x; e++) o += g_counts[e];
        soff[threadIdx.x] = o;
        if (blockIdx.x == 0) {
            g_offsets[threadIdx.x] = o;
            if (threadIdx.x == NEXP - 1) g_offsets[NEXP] = o + g_counts[NEXP - 1];
        }
    }
    __syncthreads();
    int t = blockIdx.x * blockDim.x + threadIdx.x;
    if (t >= TKN) return;
    #pragma unroll
    for (int k = 0; k < 2; k++) {
        int e = g_topE[2 * t + k];
        int pos = soff[e] + atomicAdd(&g_cursor[e], 1);
        g_rowTok[pos]  = t;
        g_rowProb[pos] = g_probs[2 * t + k];
    }
}

// ---------------------------------------------------------------------------
// Zero the output buffer (it is poisoned before timing)
// ---------------------------------------------------------------------------
__global__ __launch_bounds__(256) void zero_out_kernel(float* __restrict__ out) {
    int i = blockIdx.x * 256 + threadIdx.x;
    ((float4*)out)[i] = make_float4(0.f, 0.f, 0.f, 0.f);
}

// ---------------------------------------------------------------------------
// GEMM tile geometry: 256 threads (8 warps, 4x2), 2 CTAs/SM.
//   K_TILE = 64 halves (128 B + 16 pad -> 144 B row stride), 3 stages.
// ---------------------------------------------------------------------------
#define KT      64
#define RSTRB   144
#define G_SA    (128 * RSTRB)
#define STAGE   (2 * G_SA)             // 36864
#define SMEM_DYN (3 * STAGE)           // 110592

// ---------------------------------------------------------------------------
// GEMM1 + SwiGLU. BM=128 rows, BF=64 f-cols (x2 matrices). Warp: 32 x 32 x2.
// B tiles loaded DIRECTLY from fp32 W1/W2 (LDG -> cvt -> STS); A via cp.async.
// ---------------------------------------------------------------------------
__global__ __launch_bounds__(256, 2)
void gemm1_kernel(const float* __restrict__ W1, const float* __restrict__ W2,
                  int ebase) {
    int e = blockIdx.z + ebase;
    int cnt = g_counts[e];
    int base = blockIdx.y * 128;
    if (base >= cnt) return;
    int off = g_offsets[e];
    int f0 = blockIdx.x * 64;

    extern __shared__ char sm[];
    __shared__ int toks[128];
    int tid = threadIdx.x;
    if (tid < 128)
        toks[tid] = (base + tid < cnt) ? g_rowTok[off + base + tid] : -1;
    __syncthreads();

    const float* W1f = W1 + ((size_t)e * FDIM + f0) * DDIM;
    const float* W2f = W2 + ((size_t)e * FDIM + f0) * DDIM;

    int w = tid >> 5, lane = tid & 31;
    int wm = w >> 1, wn = w & 1;
    int g = lane >> 2, tig = lane & 3;

    uint32_t smbase = smem_u32(sm);
    uint32_t arow  = (uint32_t)((wm * 32 + (lane & 15)) * RSTRB + (lane >> 4) * 16);
    uint32_t brow4 = (uint32_t)((wn * 32 + (lane & 7) + ((lane >> 4) & 1) * 8) * RSTRB
                                + ((lane >> 3) & 1) * 16);

    float acc1[2][4][4], acc2[2][4][4];
    #pragma unroll
    for (int mi = 0; mi < 2; mi++)
        #pragma unroll
        for (int ni = 0; ni < 4; ni++)
            #pragma unroll
            for (int q = 0; q < 4; q++) { acc1[mi][ni][q] = 0.f; acc2[mi][ni][q] = 0.f; }

    const int NKT = DDIM / KT;   // 16

    // A tile via cp.async (fp16 source)
    auto load_A = [&](int s, int k0) {
        char* smA = sm + s * STAGE;
        #pragma unroll
        for (int j = 0; j < 4; j++) {
            int slot = tid + j * 256;
            int row = slot >> 3, q = slot & 7;
            int tok = toks[row];
            const __half* src = g_xh + (size_t)(tok >= 0 ? tok : 0) * DDIM + k0 + q * 8;
            cp16(smA + row * RSTRB + q * 16, src, tok >= 0 ? 16 : 0);
        }
    };
    // B tile: fp32 weights -> fp16 smem (LDG + cvt + STS)
    auto load_B = [&](int s, int k0) {
        char* smB = sm + s * STAGE + G_SA;
        #pragma unroll
        for (int j = 0; j < 4; j++) {
            int slot = tid + j * 256;          // 1024 chunks of 16B dst
            int r = slot >> 3, q = slot & 7;
            int mat = r >> 6, rw = r & 63;
            const float* src = (mat ? W2f : W1f) + (size_t)rw * DDIM + k0 + q * 8;
            *(uint4*)(smB + r * RSTRB + q * 16) = cvt8(src);
        }
    };

    load_A(0, 0);  load_B(0, 0);  CP_COMMIT();
    load_A(1, KT); load_B(1, KT); CP_COMMIT();

    for (int kt = 0; kt < NKT; kt++) {
        if (kt + 1 < NKT) CP_WAIT(1); else CP_WAIT(0);
        __syncthreads();

        int s = kt % 3;
        uint32_t sa = smbase + s * STAGE;
        uint32_t ub = sa + G_SA;

        #pragma unroll
        for (int ks = 0; ks < 4; ks++) {
            uint32_t a0[4], a1[4], b1f[2][4], b2f[2][4];
            ldsm4(a0, sa + arow + ks * 32);
            ldsm4(a1, sa + arow + 16 * RSTRB + ks * 32);
            #pragma unroll
            for (int n2 = 0; n2 < 2; n2++) {
                ldsm4(b1f[n2], ub + brow4 + n2 * 16 * RSTRB + ks * 32);
                ldsm4(b2f[n2], ub + brow4 + (64 + n2 * 16) * RSTRB + ks * 32);
            }
            #pragma unroll
            for (int n2 = 0; n2 < 2; n2++) {
                #pragma unroll
                for (int h = 0; h < 2; h++) {
                    mma_f16(acc1[0][n2 * 2 + h], a0, b1f[n2][2 * h], b1f[n2][2 * h + 1]);
                    mma_f16(acc1[1][n2 * 2 + h], a1, b1f[n2][2 * h], b1f[n2][2 * h + 1]);
                    mma_f16(acc2[0][n2 * 2 + h], a0, b2f[n2][2 * h], b2f[n2][2 * h + 1]);
                    mma_f16(acc2[1][n2 * 2 + h], a1, b2f[n2][2 * h], b2f[n2][2 * h + 1]);
                }
            }
        }

        if (kt + 2 < NKT) {
            load_A((kt + 2) % 3, (kt + 2) * KT);
            load_B((kt + 2) % 3, (kt + 2) * KT);
            CP_COMMIT();
        }
    }

    // Epilogue: SwiGLU -> Hh (fp16)
    #pragma unroll
    for (int mi = 0; mi < 2; mi++) {
        int r0 = base + wm * 32 + mi * 16 + g;
        #pragma unroll
        for (int ni = 0; ni < 4; ni++) {
            int col = f0 + wn * 32 + ni * 8 + tig * 2;
            #pragma unroll
            for (int half = 0; half < 2; half++) {
                int row = r0 + half * 8;
                if (row < cnt) {
                    float h1a = acc1[mi][ni][half * 2 + 0];
                    float h1b = acc1[mi][ni][half * 2 + 1];
                    float h2a = acc2[mi][ni][half * 2 + 0];
                    float h2b = acc2[mi][ni][half * 2 + 1];
                    float oa = h1a / (1.f + __expf(-h1a)) * h2a;
                    float ob = h1b / (1.f + __expf(-h1b)) * h2b;
                    *(__half2*)(g_Hh + (size_t)(off + row) * FDIM + col) =
                        __floats2half2_rn(oa, ob);
                }
            }
        }
    }
}

// ---------------------------------------------------------------------------
// GEMM2 + fused combine: out[tok] += prob * (H[row] . W3[e]^T)   (fp16 W3h)
// ---------------------------------------------------------------------------
__global__ __launch_bounds__(256, 2)
void gemm2_kernel(float* __restrict__ out, int ebase) {
    int e = blockIdx.z + ebase;
    int cnt = g_counts[e];
    int base = blockIdx.y * 128;
    if (base >= cnt) return;
    int off = g_offsets[e];
    int d0 = blockIdx.x * 128;

    extern __shared__ char sm[];
    int tid = threadIdx.x;

    const __half* W3e = g_W3h + ((size_t)e * DDIM + d0) * FDIM;
    const __half* Ab  = g_Hh + (size_t)(off + base) * FDIM;
    int arows = cnt - base;

    int w = tid >> 5, lane = tid & 31;
    int wm = w >> 1, wn = w & 1;
    int g = lane >> 2, tig = lane & 3;

    uint32_t smbase = smem_u32(sm);
    uint32_t arow  = (uint32_t)((wm * 32 + (lane & 15)) * RSTRB + (lane >> 4) * 16);
    uint32_t brow4 = (uint32_t)((wn * 64 + (lane & 7) + ((lane >> 4) & 1) * 8) * RSTRB
                                + ((lane >> 3) & 1) * 16);

    float acc[2][8][4];
    #pragma unroll
    for (int mi = 0; mi < 2; mi++)
        #pragma unroll
        for (int ni = 0; ni < 8; ni++)
            #pragma unroll
            for (int q = 0; q < 4; q++) acc[mi][ni][q] = 0.f;

    const int NKT = FDIM / KT;   // 32

    auto load_stage = [&](int s, int k0) {
        char* smA = sm + s * STAGE;
        char* smB = smA + G_SA;
        #pragma unroll
        for (int j = 0; j < 4; j++) {
            int slot = tid + j * 256;
            int row = slot >> 3, q = slot & 7;
            const __half* src = Ab + (size_t)(row < arows ? row : 0) * FDIM + k0 + q * 8;
            cp16(smA + row * RSTRB + q * 16, src, row < arows ? 16 : 0);
        }
        #pragma unroll
        for (int j = 0; j < 4; j++) {
            int slot = tid + j * 256;
            int r = slot >> 3, q = slot & 7;
            const __half* src = W3e + (size_t)r * FDIM + k0 + q * 8;
            cp16(smB + r * RSTRB + q * 16, src, 16);
        }
    };

    load_stage(0, 0);  CP_COMMIT();
    load_stage(1, KT); CP_COMMIT();

    for (int kt = 0; kt < NKT; kt++) {
        if (kt + 1 < NKT) CP_WAIT(1); else CP_WAIT(0);
        __syncthreads();

        int s = kt % 3;
        uint32_t sa = smbase + s * STAGE;
        uint32_t ub = sa + G_SA;

        #pragma unroll
        for (int ks = 0; ks < 4; ks++) {
            uint32_t a0[4], a1[4], bf[4][4];
            ldsm4(a0, sa + arow + ks * 32);
            ldsm4(a1, sa + arow + 16 * RSTRB + ks * 32);
            #pragma unroll
            for (int n2 = 0; n2 < 4; n2++)
                ldsm4(bf[n2], ub + brow4 + n2 * 16 * RSTRB + ks * 32);
            #pragma unroll
            for (int n2 = 0; n2 < 4; n2++) {
                #pragma unroll
                for (int h = 0; h < 2; h++) {
                    mma_f16(acc[0][n2 * 2 + h], a0, bf[n2][2 * h], bf[n2][2 * h + 1]);
                    mma_f16(acc[1][n2 * 2 + h], a1, bf[n2][2 * h], bf[n2][2 * h + 1]);
                }
            }
        }

        if (kt + 2 < NKT) { load_stage((kt + 2) % 3, (kt + 2) * KT); CP_COMMIT(); }
    }

    // Fused combine epilogue: scale by gate prob, atomicAdd into out[token]
    #pragma unroll
    for (int mi = 0; mi < 2; mi++) {
        int rb = wm * 32 + mi * 16 + g;
        #pragma unroll
        for (int half = 0; half < 2; half++) {
            int row = base + rb + half * 8;
            if (row < cnt) {
                int   tok = g_rowTok[off + row];
                float p   = g_rowProb[off + row];
                float* op = out + (size_t)tok * DDIM + d0;
                #pragma unroll
                for (int ni = 0; ni < 8; ni++) {
                    int col = wn * 64 + ni * 8 + tig * 2;
                    atomicAdd(op + col,     p * acc[mi][ni][half * 2 + 0]);
                    atomicAdd(op + col + 1, p * acc[mi][ni][half * 2 + 1]);
                }
            }
        }
    }
}

// ---------------------------------------------------------------------------
// Entry point — gemm1 no longer gated on any weight convert:
//   side: convert_w3, zero_out -(evZ)-> [evA] gemm2_lo -(evLo)->
//   main: reset, gating, scatter, gemm1_lo -(evA)-> gemm1_hi,
//         [evZ] gemm2_hi, [evLo] join
// ---------------------------------------------------------------------------
extern "C" void kernel_launch(void* const* d_in, const int* in_sizes, int n_in,
                              void* d_out, int out_size) {
    (void)in_sizes; (void)n_in; (void)out_size;
    const float* x  = (const float*)d_in[0];
    const float* Wg = (const float*)d_in[1];
    const float* W1 = (const float*)d_in[2];
    const float* W2 = (const float*)d_in[3];
    const float* W3 = (const float*)d_in[4];
    float* out = (float*)d_out;

    cudaFuncSetAttribute(gemm1_kernel, cudaFuncAttributeMaxDynamicSharedMemorySize, SMEM_DYN);
    cudaFuncSetAttribute(gemm2_kernel, cudaFuncAttributeMaxDynamicSharedMemorySize, SMEM_DYN);

    cudaStream_t s1;
    cudaStreamCreateWithFlags(&s1, cudaStreamNonBlocking);
    cudaEvent_t ev0, evZ, evA, evLo;
    cudaEventCreateWithFlags(&ev0,  cudaEventDisableTiming);
    cudaEventCreateWithFlags(&evZ,  cudaEventDisableTiming);
    cudaEventCreateWithFlags(&evA,  cudaEventDisableTiming);
    cudaEventCreateWithFlags(&evLo, cudaEventDisableTiming);

    // Fork side stream from the main (capture) stream
    cudaEventRecord(ev0, 0);
    cudaStreamWaitEvent(s1, ev0, 0);

    // Side stream: W3 convert + zero-fill (fully hidden under gemm1)
    convert_w3_kernel<<<(int)(WP / 1024), 256, 0, s1>>>(W3);
    zero_out_kernel<<<TKN * DDIM / 1024, 256, 0, s1>>>(out);
    cudaEventRecord(evZ, s1);

    // Main stream: routing, then gemm1 immediately (no weight-convert gate)
    reset_kernel<<<1, 32>>>();
    gating_kernel<<<TKN, 256>>>(x, Wg);
    scatter_kernel<<<TKN / 256, 256>>>();

    gemm1_kernel<<<dim3(FDIM / 64, TKN / 128, 4), 256, SMEM_DYN>>>(W1, W2, 0);
    cudaEventRecord(evA, 0);
    gemm1_kernel<<<dim3(FDIM / 64, TKN / 128, 4), 256, SMEM_DYN>>>(W1, W2, 4);

    // gemm2 lo on side stream, concurrent with gemm1 hi
    cudaStreamWaitEvent(s1, evA, 0);
    gemm2_kernel<<<dim3(DDIM / 128, TKN / 128, 4), 256, SMEM_DYN, s1>>>(out, 0);
    cudaEventRecord(evLo, s1);

    // gemm2 hi on main stream (after gemm1 hi, needs W3h + zeroed out)
    cudaStreamWaitEvent(0, evZ, 0);
    gemm2_kernel<<<dim3(DDIM / 128, TKN / 128, 4), 256, SMEM_DYN>>>(out, 4);

    // Join side stream back into capture origin
    cudaStreamWaitEvent(0, evLo, 0);
}

// round 17
// speedup vs baseline: 1.1405x; 1.1405x over previous
#include <cuda_runtime.h>
#include <cuda_fp16.h>
#include <cstdint>
#include <math.h>

// Problem constants
#define TKN   4096
#define DDIM  1024
#define FDIM  2048
#define NEXP  8
#define NASS  (TKN * 2)

// ---------------------------------------------------------------------------
// Scratch (device globals)
// ---------------------------------------------------------------------------
__device__ int   g_counts[NEXP];
__device__ int   g_offsets[NEXP + 1];
__device__ int   g_cursor[NEXP];
__device__ int   g_rowTok[NASS];
__device__ float g_rowProb[NASS];
__device__ float g_probs[NASS];
__device__ int   g_topE[NASS];

__device__ __align__(16) __half g_xh[(size_t)TKN * DDIM];
__device__ __align__(16) __half g_W1h[(size_t)NEXP * FDIM * DDIM];
__device__ __align__(16) __half g_W2h[(size_t)NEXP * FDIM * DDIM];
__device__ __align__(16) __half g_W3h[(size_t)NEXP * DDIM * FDIM];
__device__ __align__(16) __half g_Hh[(size_t)NASS * FDIM];

// ---------------------------------------------------------------------------
// Helpers
// ---------------------------------------------------------------------------
__device__ __forceinline__ uint32_t smem_u32(const void* p) {
    uint32_t a;
    asm("{ .reg .u64 t; cvta.to.shared.u64 t, %1; cvt.u32.u64 %0, t; }" : "=r"(a) : "l"(p));
    return a;
}
__device__ __forceinline__ void cp16(void* dst, const void* src, int zfill) {
    uint32_t d = smem_u32(dst);
    asm volatile("cp.async.cg.shared.global [%0], [%1], 16, %2;"
                 :: "r"(d), "l"(src), "r"(zfill) : "memory");
}
#define CP_COMMIT() asm volatile("cp.async.commit_group;" ::: "memory")
#define CP_WAIT(n)  asm volatile("cp.async.wait_group %0;" :: "n"(n) : "memory")

__device__ __forceinline__ void mma_f16(float* c, const uint32_t* a,
                                        uint32_t b0, uint32_t b1) {
    asm volatile(
        "mma.sync.aligned.m16n8k16.row.col.f32.f16.f16.f32 "
        "{%0,%1,%2,%3}, {%4,%5,%6,%7}, {%8,%9}, {%0,%1,%2,%3};"
        : "+f"(c[0]), "+f"(c[1]), "+f"(c[2]), "+f"(c[3])
        : "r"(a[0]), "r"(a[1]), "r"(a[2]), "r"(a[3]), "r"(b0), "r"(b1));
}
__device__ __forceinline__ void ldsm4(uint32_t* r, uint32_t a) {
    asm volatile("ldmatrix.sync.aligned.m8n8.x4.shared.b16 {%0,%1,%2,%3}, [%4];"
                 : "=r"(r[0]), "=r"(r[1]), "=r"(r[2]), "=r"(r[3]) : "r"(a));
}

// Streaming (evict-first) float4 load — keeps fp32 weight stream out of L2
__device__ __forceinline__ float4 ldcs4(const float4* p) {
    float4 v;
    asm volatile("ld.global.cs.v4.f32 {%0,%1,%2,%3}, [%4];"
                 : "=f"(v.x), "=f"(v.y), "=f"(v.z), "=f"(v.w) : "l"(p));
    return v;
}

// ---------------------------------------------------------------------------
// Weight converts — 4 independent pair-conversions per thread for MLP.
// fp32 reads are streaming (.cs): read-once data must not evict fp16 output
// lines that gemm1/gemm2 will consume from L2.
// ---------------------------------------------------------------------------
#define W4 (NEXP * FDIM * DDIM / 4)
#define WP ((long)W4 / 2)

__device__ __forceinline__ void cvt_pair(const float4* s, uint4* d, long j) {
    float4 a = ldcs4(s + 2 * j), b = ldcs4(s + 2 * j + 1);
    __half2 h0 = __floats2half2_rn(a.x, a.y);
    __half2 h1 = __floats2half2_rn(a.z, a.w);
    __half2 h2 = __floats2half2_rn(b.x, b.y);
    __half2 h3 = __floats2half2_rn(b.z, b.w);
    uint4 o;
    o.x = *reinterpret_cast<uint32_t*>(&h0);
    o.y = *reinterpret_cast<uint32_t*>(&h1);
    o.z = *reinterpret_cast<uint32_t*>(&h2);
    o.w = *reinterpret_cast<uint32_t*>(&h3);
    d[j] = o;
}

__global__ __launch_bounds__(256) void convert_w12_kernel(
    const float* __restrict__ W1, const float* __restrict__ W2) {
    long p0 = (long)blockIdx.x * 1024 + threadIdx.x;
    #pragma unroll
    for (int u = 0; u < 4; u++) {
        long p = p0 + u * 256;
        if (p < WP)           cvt_pair((const float4*)W1, (uint4*)g_W1h, p);
        else if (p < 2 * WP)  cvt_pair((const float4*)W2, (uint4*)g_W2h, p - WP);
    }
}

__global__ __launch_bounds__(256) void convert_w3_kernel(const float* __restrict__ W3) {
    long p0 = (long)blockIdx.x * 1024 + threadIdx.x;
    #pragma unroll
    for (int u = 0; u < 4; u++) {
        long p = p0 + u * 256;
        if (p < WP) cvt_pair((const float4*)W3, (uint4*)g_W3h, p);
    }
}

// ---------------------------------------------------------------------------
// Reset routing counters
// ---------------------------------------------------------------------------
__global__ void reset_kernel() {
    if (threadIdx.x < NEXP) {
        g_counts[threadIdx.x] = 0;
        g_cursor[threadIdx.x] = 0;
    }
}

// ---------------------------------------------------------------------------
// Gating: top-2 + softmax + counts; ALSO converts this token's x row to fp16
// ---------------------------------------------------------------------------
__global__ __launch_bounds__(256) void gating_kernel(
    const float* __restrict__ x, const float* __restrict__ Wg) {
    int t = blockIdx.x;
    __shared__ float xs[DDIM];
    __shared__ float sc[NEXP];
    for (int i = threadIdx.x; i < DDIM; i += 256)
        xs[i] = x[(size_t)t * DDIM + i];
    __syncthreads();

    {
        int i4 = threadIdx.x * 4;
        __half2 ha = __floats2half2_rn(xs[i4],     xs[i4 + 1]);
        __half2 hb = __floats2half2_rn(xs[i4 + 2], xs[i4 + 3]);
        uint2 o;
        o.x = *reinterpret_cast<uint32_t*>(&ha);
        o.y = *reinterpret_cast<uint32_t*>(&hb);
        *(uint2*)(g_xh + (size_t)t * DDIM + i4) = o;
    }

    int w = threadIdx.x >> 5, lane = threadIdx.x & 31;
    const float* wg = Wg + (size_t)w * DDIM;
    float acc = 0.f;
    #pragma unroll 8
    for (int i = lane; i < DDIM; i += 32) acc += xs[i] * wg[i];
    #pragma unroll
    for (int o = 16; o; o >>= 1) acc += __shfl_xor_sync(0xFFFFFFFFu, acc, o);
    if (lane == 0) sc[w] = acc;
    __syncthreads();
    if (threadIdx.x == 0) {
        int e0 = 0; float s0 = sc[0];
        #pragma unroll
        for (int e = 1; e < NEXP; e++)
            if (sc[e] > s0) { s0 = sc[e]; e0 = e; }
        int e1 = -1; float s1 = -1e30f;
        #pragma unroll
        for (int e = 0; e < NEXP; e++)
            if (e != e0 && sc[e] > s1) { s1 = sc[e]; e1 = e; }
        float z = expf(s1 - s0);
        float inv = 1.f / (1.f + z);
        g_topE[2 * t] = e0;  g_topE[2 * t + 1] = e1;
        g_probs[2 * t] = inv; g_probs[2 * t + 1] = z * inv;
        atomicAdd(&g_counts[e0], 1);
        atomicAdd(&g_counts[e1], 1);
    }
}

// ---------------------------------------------------------------------------
// Scatter (with local scan of the 8 expert counts); records per-row token+prob
// ---------------------------------------------------------------------------
__global__ __launch_bounds__(256) void scatter_kernel() {
    __shared__ int soff[NEXP];
    if (threadIdx.x < NEXP) {
        int o = 0;
        for (int e = 0; e < threadIdx.x; e++) o += g_counts[e];
        soff[threadIdx.x] = o;
        if (blockIdx.x == 0) {
            g_offsets[threadIdx.x] = o;
            if (threadIdx.x == NEXP - 1) g_offsets[NEXP] = o + g_counts[NEXP - 1];
        }
    }
    __syncthreads();
    int t = blockIdx.x * blockDim.x + threadIdx.x;
    if (t >= TKN) return;
    #pragma unroll
    for (int k = 0; k < 2; k++) {
        int e = g_topE[2 * t + k];
        int pos = soff[e] + atomicAdd(&g_cursor[e], 1);
        g_rowTok[pos]  = t;
        g_rowProb[pos] = g_probs[2 * t + k];
    }
}

// ---------------------------------------------------------------------------
// Zero the output buffer (it is poisoned before timing)
// ---------------------------------------------------------------------------
__global__ __launch_bounds__(256) void zero_out_kernel(float* __restrict__ out) {
    int i = blockIdx.x * 256 + threadIdx.x;
    ((float4*)out)[i] = make_float4(0.f, 0.f, 0.f, 0.f);
}

// ---------------------------------------------------------------------------
// GEMM tile geometry: 256 threads (8 warps, 4x2), 2 CTAs/SM.
//   K_TILE = 64 halves (128 B + 16 pad -> 144 B row stride), 3 stages.
// ---------------------------------------------------------------------------
#define KT      64
#define RSTRB   144
#define G_SA    (128 * RSTRB)
#define STAGE   (2 * G_SA)             // 36864
#define SMEM_DYN (3 * STAGE)           // 110592

// ---------------------------------------------------------------------------
// GEMM1 + SwiGLU. BM=128 rows, BF=64 f-cols (x2 matrices). Warp: 32 x 32 x2.
// ---------------------------------------------------------------------------
__global__ __launch_bounds__(256, 2)
void gemm1_kernel(int ebase) {
    int e = blockIdx.z + ebase;
    int cnt = g_counts[e];
    int base = blockIdx.y * 128;
    if (base >= cnt) return;
    int off = g_offsets[e];
    int f0 = blockIdx.x * 64;

    extern __shared__ char sm[];
    __shared__ int toks[128];
    int tid = threadIdx.x;
    if (tid < 128)
        toks[tid] = (base + tid < cnt) ? g_rowTok[off + base + tid] : -1;
    __syncthreads();

    const __half* W1e = g_W1h + ((size_t)e * FDIM + f0) * DDIM;
    const __half* W2e = g_W2h + ((size_t)e * FDIM + f0) * DDIM;

    int w = tid >> 5, lane = tid & 31;
    int wm = w >> 1, wn = w & 1;
    int g = lane >> 2, tig = lane & 3;

    uint32_t smbase = smem_u32(sm);
    uint32_t arow  = (uint32_t)((wm * 32 + (lane & 15)) * RSTRB + (lane >> 4) * 16);
    uint32_t brow4 = (uint32_t)((wn * 32 + (lane & 7) + ((lane >> 4) & 1) * 8) * RSTRB
                                + ((lane >> 3) & 1) * 16);

    float acc1[2][4][4], acc2[2][4][4];
    #pragma unroll
    for (int mi = 0; mi < 2; mi++)
        #pragma unroll
        for (int ni = 0; ni < 4; ni++)
            #pragma unroll
            for (int q = 0; q < 4; q++) { acc1[mi][ni][q] = 0.f; acc2[mi][ni][q] = 0.f; }

    const int NKT = DDIM / KT;   // 16

    auto load_stage = [&](int s, int k0) {
        char* smA = sm + s * STAGE;
        char* smB = smA + G_SA;
        #pragma unroll
        for (int j = 0; j < 4; j++) {
            int slot = tid + j * 256;
            int row = slot >> 3, q = slot & 7;
            int tok = toks[row];
            const __half* src = g_xh + (size_t)(tok >= 0 ? tok : 0) * DDIM + k0 + q * 8;
            cp16(smA + row * RSTRB + q * 16, src, tok >= 0 ? 16 : 0);
        }
        #pragma unroll
        for (int j = 0; j < 4; j++) {
            int slot = tid + j * 256;
            int r = slot >> 3, q = slot & 7;
            int mat = r >> 6, rw = r & 63;
            const __half* src = (mat ? W2e : W1e) + (size_t)rw * DDIM + k0 + q * 8;
            cp16(smB + r * RSTRB + q * 16, src, 16);
        }
    };

    load_stage(0, 0);  CP_COMMIT();
    load_stage(1, KT); CP_COMMIT();

    for (int kt = 0; kt < NKT; kt++) {
        if (kt + 1 < NKT) CP_WAIT(1); else CP_WAIT(0);
        __syncthreads();

        int s = kt % 3;
        uint32_t sa = smbase + s * STAGE;
        uint32_t ub = sa + G_SA;

        #pragma unroll
        for (int ks = 0; ks < 4; ks++) {
            uint32_t a0[4], a1[4], b1f[2][4], b2f[2][4];
            ldsm4(a0, sa + arow + ks * 32);
            ldsm4(a1, sa + arow + 16 * RSTRB + ks * 32);
            #pragma unroll
            for (int n2 = 0; n2 < 2; n2++) {
                ldsm4(b1f[n2], ub + brow4 + n2 * 16 * RSTRB + ks * 32);
                ldsm4(b2f[n2], ub + brow4 + (64 + n2 * 16) * RSTRB + ks * 32);
            }
            #pragma unroll
            for (int n2 = 0; n2 < 2; n2++) {
                #pragma unroll
                for (int h = 0; h < 2; h++) {
                    mma_f16(acc1[0][n2 * 2 + h], a0, b1f[n2][2 * h], b1f[n2][2 * h + 1]);
                    mma_f16(acc1[1][n2 * 2 + h], a1, b1f[n2][2 * h], b1f[n2][2 * h + 1]);
                    mma_f16(acc2[0][n2 * 2 + h], a0, b2f[n2][2 * h], b2f[n2][2 * h + 1]);
                    mma_f16(acc2[1][n2 * 2 + h], a1, b2f[n2][2 * h], b2f[n2][2 * h + 1]);
                }
            }
        }

        if (kt + 2 < NKT) { load_stage((kt + 2) % 3, (kt + 2) * KT); CP_COMMIT(); }
    }

    // Epilogue: SwiGLU -> Hh (fp16)
    #pragma unroll
    for (int mi = 0; mi < 2; mi++) {
        int r0 = base + wm * 32 + mi * 16 + g;
        #pragma unroll
        for (int ni = 0; ni < 4; ni++) {
            int col = f0 + wn * 32 + ni * 8 + tig * 2;
            #pragma unroll
            for (int half = 0; half < 2; half++) {
                int row = r0 + half * 8;
                if (row < cnt) {
                    float h1a = acc1[mi][ni][half * 2 + 0];
                    float h1b = acc1[mi][ni][half * 2 + 1];
                    float h2a = acc2[mi][ni][half * 2 + 0];
                    float h2b = acc2[mi][ni][half * 2 + 1];
                    float oa = h1a / (1.f + __expf(-h1a)) * h2a;
                    float ob = h1b / (1.f + __expf(-h1b)) * h2b;
                    *(__half2*)(g_Hh + (size_t)(off + row) * FDIM + col) =
                        __floats2half2_rn(oa, ob);
                }
            }
        }
    }
}

// ---------------------------------------------------------------------------
// GEMM2 + fused combine: out[tok] += prob * (H[row] . W3[e]^T)
// ---------------------------------------------------------------------------
__global__ __launch_bounds__(256, 2)
void gemm2_kernel(float* __restrict__ out, int ebase) {
    int e = blockIdx.z + ebase;
    int cnt = g_counts[e];
    int base = blockIdx.y * 128;
    if (base >= cnt) return;
    int off = g_offsets[e];
    int d0 = blockIdx.x * 128;

    extern __shared__ char sm[];
    int tid = threadIdx.x;

    const __half* W3e = g_W3h + ((size_t)e * DDIM + d0) * FDIM;
    const __half* Ab  = g_Hh + (size_t)(off + base) * FDIM;
    int arows = cnt - base;

    int w = tid >> 5, lane = tid & 31;
    int wm = w >> 1, wn = w & 1;
    int g = lane >> 2, tig = lane & 3;

    uint32_t smbase = smem_u32(sm);
    uint32_t arow  = (uint32_t)((wm * 32 + (lane & 15)) * RSTRB + (lane >> 4) * 16);
    uint32_t brow4 = (uint32_t)((wn * 64 + (lane & 7) + ((lane >> 4) & 1) * 8) * RSTRB
                                + ((lane >> 3) & 1) * 16);

    float acc[2][8][4];
    #pragma unroll
    for (int mi = 0; mi < 2; mi++)
        #pragma unroll
        for (int ni = 0; ni < 8; ni++)
            #pragma unroll
            for (int q = 0; q < 4; q++) acc[mi][ni][q] = 0.f;

    const int NKT = FDIM / KT;   // 32

    auto load_stage = [&](int s, int k0) {
        char* smA = sm + s * STAGE;
        char* smB = smA + G_SA;
        #pragma unroll
        for (int j = 0; j < 4; j++) {
            int slot = tid + j * 256;
            int row = slot >> 3, q = slot & 7;
            const __half* src = Ab + (size_t)(row < arows ? row : 0) * FDIM + k0 + q * 8;
            cp16(smA + row * RSTRB + q * 16, src, row < arows ? 16 : 0);
        }
        #pragma unroll
        for (int j = 0; j < 4; j++) {
            int slot = tid + j * 256;
            int r = slot >> 3, q = slot & 7;
            const __half* src = W3e + (size_t)r * FDIM + k0 + q * 8;
            cp16(smB + r * RSTRB + q * 16, src, 16);
        }
    };

    load_stage(0, 0);  CP_COMMIT();
    load_stage(1, KT); CP_COMMIT();

    for (int kt = 0; kt < NKT; kt++) {
        if (kt + 1 < NKT) CP_WAIT(1); else CP_WAIT(0);
        __syncthreads();

        int s = kt % 3;
        uint32_t sa = smbase + s * STAGE;
        uint32_t ub = sa + G_SA;

        #pragma unroll
        for (int ks = 0; ks < 4; ks++) {
            uint32_t a0[4], a1[4], bf[4][4];
            ldsm4(a0, sa + arow + ks * 32);
            ldsm4(a1, sa + arow + 16 * RSTRB + ks * 32);
            #pragma unroll
            for (int n2 = 0; n2 < 4; n2++)
                ldsm4(bf[n2], ub + brow4 + n2 * 16 * RSTRB + ks * 32);
            #pragma unroll
            for (int n2 = 0; n2 < 4; n2++) {
                #pragma unroll
                for (int h = 0; h < 2; h++) {
                    mma_f16(acc[0][n2 * 2 + h], a0, bf[n2][2 * h], bf[n2][2 * h + 1]);
                    mma_f16(acc[1][n2 * 2 + h], a1, bf[n2][2 * h], bf[n2][2 * h + 1]);
                }
            }
        }

        if (kt + 2 < NKT) { load_stage((kt + 2) % 3, (kt + 2) * KT); CP_COMMIT(); }
    }

    // Fused combine epilogue: scale by gate prob, atomicAdd into out[token]
    #pragma unroll
    for (int mi = 0; mi < 2; mi++) {
        int rb = wm * 32 + mi * 16 + g;
        #pragma unroll
        for (int half = 0; half < 2; half++) {
            int row = base + rb + half * 8;
            if (row < cnt) {
                int   tok = g_rowTok[off + row];
                float p   = g_rowProb[off + row];
                float* op = out + (size_t)tok * DDIM + d0;
                #pragma unroll
                for (int ni = 0; ni < 8; ni++) {
                    int col = wn * 64 + ni * 8 + tig * 2;
                    atomicAdd(op + col,     p * acc[mi][ni][half * 2 + 0]);
                    atomicAdd(op + col + 1, p * acc[mi][ni][half * 2 + 1]);
                }
            }
        }
    }
}

// ---------------------------------------------------------------------------
// Entry point — proven R11/R15 schedule:
//   side: convert_w12 -(evW12)-> convert_w3, zero_out -(evZ)->
//         [evA] gemm2_lo -(evLo)->
//   main: reset, gating, scatter, [evW12] gemm1_lo -(evA)-> gemm1_hi,
//         [evZ] gemm2_hi, [evLo] join
// ---------------------------------------------------------------------------
extern "C" void kernel_launch(void* const* d_in, const int* in_sizes, int n_in,
                              void* d_out, int out_size) {
    (void)in_sizes; (void)n_in; (void)out_size;
    const float* x  = (const float*)d_in[0];
    const float* Wg = (const float*)d_in[1];
    const float* W1 = (const float*)d_in[2];
    const float* W2 = (const float*)d_in[3];
    const float* W3 = (const float*)d_in[4];
    float* out = (float*)d_out;

    cudaFuncSetAttribute(gemm1_kernel, cudaFuncAttributeMaxDynamicSharedMemorySize, SMEM_DYN);
    cudaFuncSetAttribute(gemm2_kernel, cudaFuncAttributeMaxDynamicSharedMemorySize, SMEM_DYN);

    cudaStream_t s1;
    cudaStreamCreateWithFlags(&s1, cudaStreamNonBlocking);
    cudaEvent_t ev0, evW12, evZ, evA, evLo;
    cudaEventCreateWithFlags(&ev0,   cudaEventDisableTiming);
    cudaEventCreateWithFlags(&evW12, cudaEventDisableTiming);
    cudaEventCreateWithFlags(&evZ,   cudaEventDisableTiming);
    cudaEventCreateWithFlags(&evA,   cudaEventDisableTiming);
    cudaEventCreateWithFlags(&evLo,  cudaEventDisableTiming);

    // Fork side stream from the main (capture) stream
    cudaEventRecord(ev0, 0);
    cudaStreamWaitEvent(s1, ev0, 0);

    // Side stream: weight converts + zero-fill
    convert_w12_kernel<<<(int)(2 * WP / 1024), 256, 0, s1>>>(W1, W2);
    cudaEventRecord(evW12, s1);
    convert_w3_kernel<<<(int)(WP / 1024), 256, 0, s1>>>(W3);
    zero_out_kernel<<<TKN * DDIM / 1024, 256, 0, s1>>>(out);
    cudaEventRecord(evZ, s1);

    // Main stream: routing
    reset_kernel<<<1, 32>>>();
    gating_kernel<<<TKN, 256>>>(x, Wg);
    scatter_kernel<<<TKN / 256, 256>>>();

    // gemm1 lo (experts 0-3), then hi (4-7) on main stream
    cudaStreamWaitEvent(0, evW12, 0);
    gemm1_kernel<<<dim3(FDIM / 64, TKN / 128, 4), 256, SMEM_DYN>>>(0);
    cudaEventRecord(evA, 0);
    gemm1_kernel<<<dim3(FDIM / 64, TKN / 128, 4), 256, SMEM_DYN>>>(4);

    // gemm2 lo on side stream, concurrent with gemm1 hi
    cudaStreamWaitEvent(s1, evA, 0);
    gemm2_kernel<<<dim3(DDIM / 128, TKN / 128, 4), 256, SMEM_DYN, s1>>>(out, 0);
    cudaEventRecord(evLo, s1);

    // gemm2 hi on main stream (after gemm1 hi, needs W3h + zeroed out)
    cudaStreamWaitEvent(0, evZ, 0);
    gemm2_kernel<<<dim3(DDIM / 128, TKN / 128, 4), 256, SMEM_DYN>>>(out, 4);

    // Join side stream back into capture origin
    cudaStreamWaitEvent(0, evLo, 0);
}